// round 14
// baseline (speedup 1.0000x reference)
#include <cuda_runtime.h>
#include <cuda_bf16.h>
#include <math.h>

// Problem dims (fixed by the reference)
#define BB 16
#define TT 4096
#define HH 1024
#define KK 128
#define VV 128
#define OO 128
#define PP 512            // 3K + V
#define MM (BB * TT)      // 65536

// Scratch (static device globals: allocation-free, graph-capturable)
__device__ float g_qkgv[(size_t)BB * TT * PP];   // 128 MB activated projections
__device__ float g_obuf[(size_t)BB * TT * VV];   // 32 MB pre-projection readout
__device__ float g_cdump[(size_t)BB * KK * VV];  // fallback c_final sink
__device__ __nv_bfloat16 g_ahi[(size_t)MM * HH]; // hidden split hi
__device__ __nv_bfloat16 g_alo[(size_t)MM * HH]; // hidden split lo
__device__ __nv_bfloat16 g_whi[(size_t)PP * HH];
__device__ __nv_bfloat16 g_wlo[(size_t)PP * HH];

typedef unsigned long long ull;

// ---------------------------------------------------------------------------
// small PTX helpers
// ---------------------------------------------------------------------------
__device__ __forceinline__ unsigned smem_u32(const void* p) {
    return (unsigned)__cvta_generic_to_shared(p);
}
__device__ __forceinline__ void cp16(void* dst, const void* src) {
    asm volatile("cp.async.cg.shared.global [%0], [%1], 16;\n"
                 :: "r"(smem_u32(dst)), "l"(src));
}
__device__ __forceinline__ void cp_commit() {
    asm volatile("cp.async.commit_group;\n");
}
__device__ __forceinline__ void cp_wait1() {
    asm volatile("cp.async.wait_group 1;\n");
}
__device__ __forceinline__ void ldsm4(unsigned r[4], const void* p) {
    unsigned a = smem_u32(p);
    asm volatile("ldmatrix.sync.aligned.m8n8.x4.shared.b16 {%0,%1,%2,%3}, [%4];\n"
                 : "=r"(r[0]), "=r"(r[1]), "=r"(r[2]), "=r"(r[3]) : "r"(a));
}
__device__ __forceinline__ void mma16816(float d[4], const unsigned a[4],
                                         unsigned b0, unsigned b1) {
    asm volatile("mma.sync.aligned.m16n8k16.row.col.f32.bf16.bf16.f32 "
                 "{%0,%1,%2,%3}, {%4,%5,%6,%7}, {%8,%9}, {%0,%1,%2,%3};\n"
                 : "+f"(d[0]), "+f"(d[1]), "+f"(d[2]), "+f"(d[3])
                 : "r"(a[0]), "r"(a[1]), "r"(a[2]), "r"(a[3]), "r"(b0), "r"(b1));
}
__device__ __forceinline__ unsigned short bfbits(__nv_bfloat16 h) {
    return ((__nv_bfloat16_raw)h).x;
}

// ---------------------------------------------------------------------------
// fp32 -> (hi, lo) bf16 split. x = hi + lo + O(2^-16 |x|).
// ---------------------------------------------------------------------------
__global__ __launch_bounds__(256) void cvt_hilo(
    const float* __restrict__ x, __nv_bfloat16* __restrict__ hi,
    __nv_bfloat16* __restrict__ lo, int n4)
{
    int i = blockIdx.x * blockDim.x + threadIdx.x;
    if (i >= n4) return;
    float4 xv = ((const float4*)x)[i];
    float xs[4] = {xv.x, xv.y, xv.z, xv.w};
    unsigned short hb[4], lb[4];
#pragma unroll
    for (int j = 0; j < 4; ++j) {
        __nv_bfloat16 h = __float2bfloat16(xs[j]);
        float r = xs[j] - __bfloat162float(h);   // exact residual
        __nv_bfloat16 l = __float2bfloat16(r);
        hb[j] = bfbits(h);
        lb[j] = bfbits(l);
    }
    uint2 uh = make_uint2(hb[0] | ((unsigned)hb[1] << 16),
                          hb[2] | ((unsigned)hb[3] << 16));
    uint2 ul = make_uint2(lb[0] | ((unsigned)lb[1] << 16),
                          lb[2] | ((unsigned)lb[3] << 16));
    ((uint2*)hi)[i] = uh;
    ((uint2*)lo)[i] = ul;
}

// ---------------------------------------------------------------------------
// GEMM1 v2 (round-13, unchanged): qkgv[M,512] = act( A @ W^T + bias )
// bf16 hi/lo split, 3-term mma.sync, CTA tile 128m x 256n, BK=32,
// 8 warps (4m x 2n), warp tile 32x128, cp.async 3-stage ring.
// ---------------------------------------------------------------------------
#define G1_STRIDE 40                       // bf16 per smem row (32 + 8 pad)
#define G1_PLANE_A (128 * G1_STRIDE)       // 5120 bf16
#define G1_PLANE_W (256 * G1_STRIDE)       // 10240 bf16
#define G1_STAGE  (2 * G1_PLANE_A + 2 * G1_PLANE_W)   // 30720 bf16
#define G1_SMEM   (3 * G1_STAGE * 2)       // 184320 B

__global__ __launch_bounds__(256) void gemm1_mma(
    const __nv_bfloat16* __restrict__ Ah, const __nv_bfloat16* __restrict__ Al,
    const __nv_bfloat16* __restrict__ Wh, const __nv_bfloat16* __restrict__ Wl,
    const float* __restrict__ bias, float* __restrict__ C)
{
    extern __shared__ __nv_bfloat16 sm[];
    const int tid  = threadIdx.x;
    const int m0   = blockIdx.y << 7;
    const int n0   = blockIdx.x << 8;      // 256-wide n tile
    const int lane = tid & 31;
    const int warp = tid >> 5;
    const int wm   = (warp & 3) << 5;      // warp m offset (0..96)
    const int wn   = (warp >> 2) << 7;     // warp n offset (0 or 128)

    const __nv_bfloat16* srcs[4] = {
        Ah + (size_t)m0 * HH, Al + (size_t)m0 * HH,
        Wh + (size_t)n0 * HH, Wl + (size_t)n0 * HH };
    const int poff[4]  = {0, G1_PLANE_A, 2 * G1_PLANE_A, 2 * G1_PLANE_A + G1_PLANE_W};

    // load one k32 block (3072 16B chunks) into stage st
    auto issue = [&](int kt, int st) {
        __nv_bfloat16* sb = sm + st * G1_STAGE;
#pragma unroll
        for (int h = 0; h < 12; ++h) {
            int c    = tid + (h << 8);           // 0..3071
            int grow = c >> 2;                   // 0..767
            int col  = (c & 3) << 3;
            int p    = (grow < 256) ? (grow >> 7) : (2 + ((grow - 256) >> 8));
            int r    = (grow < 256) ? (grow & 127) : ((grow - 256) & 255);
            cp16(sb + poff[p] + r * G1_STRIDE + col,
                 srcs[p] + (size_t)r * HH + kt * 32 + col);
        }
        cp_commit();
    };

    float acc[2][16][4];
#pragma unroll
    for (int im = 0; im < 2; ++im)
#pragma unroll
        for (int j = 0; j < 16; ++j)
#pragma unroll
            for (int r = 0; r < 4; ++r) acc[im][j][r] = 0.f;

    issue(0, 0);
    issue(1, 1);

    const int arow  = lane & 15;
    const int acolb = (lane >> 4) << 3;
    const int brow  = ((lane & 16) >> 1) + (lane & 7);
    const int bcolb = ((lane >> 3) & 1) << 3;

    const int nk = HH / 32;                // 32
    for (int kt = 0; kt < nk; ++kt) {
        cp_wait1();
        __syncthreads();
        const __nv_bfloat16* st  = sm + (kt % 3) * G1_STAGE;
        const __nv_bfloat16* sAh = st;
        const __nv_bfloat16* sAl = st + G1_PLANE_A;
        const __nv_bfloat16* sWh = st + 2 * G1_PLANE_A;
        const __nv_bfloat16* sWl = st + 2 * G1_PLANE_A + G1_PLANE_W;
#pragma unroll
        for (int ks = 0; ks < 2; ++ks) {
            const int ko = ks << 4;
            unsigned aH[2][4], aL[2][4];
#pragma unroll
            for (int im = 0; im < 2; ++im) {
                int r = wm + (im << 4) + arow;
                ldsm4(aH[im], sAh + r * G1_STRIDE + ko + acolb);
                ldsm4(aL[im], sAl + r * G1_STRIDE + ko + acolb);
            }
#pragma unroll
            for (int ng = 0; ng < 8; ++ng) {
                int r = wn + (ng << 4) + brow;
                unsigned bh[4], bl[4];
                ldsm4(bh, sWh + r * G1_STRIDE + ko + bcolb);
                ldsm4(bl, sWl + r * G1_STRIDE + ko + bcolb);
#pragma unroll
                for (int im = 0; im < 2; ++im) {
                    mma16816(acc[im][ng * 2],     aH[im], bh[0], bh[1]);
                    mma16816(acc[im][ng * 2 + 1], aH[im], bh[2], bh[3]);
                    mma16816(acc[im][ng * 2],     aH[im], bl[0], bl[1]);
                    mma16816(acc[im][ng * 2 + 1], aH[im], bl[2], bl[3]);
                    mma16816(acc[im][ng * 2],     aL[im], bh[0], bh[1]);
                    mma16816(acc[im][ng * 2 + 1], aL[im], bh[2], bh[3]);
                }
            }
        }
        if (kt + 2 < nk) issue(kt + 2, (kt + 2) % 3);
        else             cp_commit();
    }

    // epilogue: bias + activation (block 0:q id, 1:k sig, 2:g sig, 3:v tanh)
    const int nblk = (n0 + wn) >> 7;
    const int act  = (nblk == 0) ? 0 : ((nblk == 3) ? 2 : 1);
    const int r0     = m0 + wm + (lane >> 2);
    const int c0base = n0 + wn + ((lane & 3) << 1);
#pragma unroll
    for (int j = 0; j < 16; ++j) {
        int col = c0base + (j << 3);
        float b0 = bias[col], b1 = bias[col + 1];
#pragma unroll
        for (int im = 0; im < 2; ++im) {
            int rb = r0 + (im << 4);
            float v0 = acc[im][j][0] + b0, v1 = acc[im][j][1] + b1;
            float v2 = acc[im][j][2] + b0, v3 = acc[im][j][3] + b1;
            if (act == 1) {
                v0 = 1.f / (1.f + __expf(-v0)); v1 = 1.f / (1.f + __expf(-v1));
                v2 = 1.f / (1.f + __expf(-v2)); v3 = 1.f / (1.f + __expf(-v3));
            } else if (act == 2) {
                v0 = tanhf(v0); v1 = tanhf(v1); v2 = tanhf(v2); v3 = tanhf(v3);
            }
            *(float2*)(C + (size_t)rb * PP + col)       = make_float2(v0, v1);
            *(float2*)(C + (size_t)(rb + 8) * PP + col) = make_float2(v2, v3);
        }
    }
}

// ---------------------------------------------------------------------------
// Sequential scan v4: k-half x v-quad tiling (min crossbar traffic).
// Grid (batch=16, v-tile=8), 256 threads = 8 warps.
// Warp w: k-half (w>>2)*64, v-quad (w&3)*4. Lane l: v = quad + (l>>3),
// 8 k's at khalf + (l&7)*8. State c[8] = c[k..k+8][v].
// q/k/g float4 loads are 4-way broadcast (1 phase each) -> ~7 phases/step/warp
// vs 13 before. Readout: 3-level shfl over the 8-lane v-group; k-halves
// combined once per 8-step group via smem (warps 4-7 post, warps 0-3 add).
// 3-ring x 8 stages, 2 groups in flight, refill right after top barrier.
// ---------------------------------------------------------------------------
#define SC_GROUPS 3
#define SC_GS     8                        // steps per group
#define SC_STAGES (SC_GROUPS * SC_GS)      // 24

__global__ __launch_bounds__(256) void scan_kernel(
    const float* __restrict__ qkgv, float* __restrict__ obuf,
    float* __restrict__ cfin)
{
    const int b   = blockIdx.x;
    const int v0  = blockIdx.y << 4;
    const int tid = threadIdx.x;
    const int w   = tid >> 5;
    const int l   = tid & 31;
    const int kh  = (w >> 2) << 6;       // k-half base: 0 or 64
    const int vq  = (w & 3) << 2;        // v-quad base within tile
    const int v   = vq + (l >> 3);       // v within tile (0..15)
    const int k0  = kh + ((l & 7) << 3); // 8 k's

    __shared__ float s[SC_STAGES][400];  // [q:128 | k:128 | g:128 | v-tile:16]
    __shared__ float pb[SC_GS][16];      // upper-k-half partials per step/v

    const float* base = qkgv + (size_t)b * TT * PP;
    float* ob = obuf + (size_t)b * TT * VV + v0 + v;

    float c[8];
#pragma unroll
    for (int i = 0; i < 8; ++i) c[i] = 0.f;

    // 100 copy threads x 16B per step
    const bool cpr = (tid < 100);
    const int goff = (tid < 96) ? (tid << 2) : (384 + v0 + ((tid - 96) << 2));
    const int soff = (tid < 96) ? (tid << 2) : (384 + ((tid - 96) << 2));

    auto issue_group = [&](int g) {
        if (cpr) {
            const int sb = (g % SC_GROUPS) * SC_GS;
            const float* p = base + (size_t)(g * SC_GS) * PP + goff;
#pragma unroll
            for (int i = 0; i < SC_GS; ++i)
                cp16(&s[sb + i][soff], p + (size_t)i * PP);
        }
        cp_commit();
    };

    issue_group(0);
    issue_group(1);

    const int NG = TT / SC_GS;           // 512 groups
    for (int g = 0; g < NG; ++g) {
        cp_wait1();                      // group g complete
        __syncthreads();                 // also guards pb reuse from group g-1

        // refill: group g+2 -> slots of group g-1 (readers passed barrier)
        if (g + 2 < NG) issue_group(g + 2);
        else            cp_commit();

        const int sb = (g % SC_GROUPS) * SC_GS;

        float a[SC_GS];
#pragma unroll
        for (int i = 0; i < SC_GS; ++i) {
            const float* st = s[sb + i];
            float4 qa = *(const float4*)&st[k0];
            float4 qb = *(const float4*)&st[k0 + 4];
            float4 ka = *(const float4*)&st[128 + k0];
            float4 kb = *(const float4*)&st[128 + k0 + 4];
            float4 ga = *(const float4*)&st[256 + k0];
            float4 gb = *(const float4*)&st[256 + k0 + 4];
            float  vv = st[384 + v];

            c[0] = fmaf(c[0], ga.x, ka.x * vv);
            c[1] = fmaf(c[1], ga.y, ka.y * vv);
            c[2] = fmaf(c[2], ga.z, ka.z * vv);
            c[3] = fmaf(c[3], ga.w, ka.w * vv);
            c[4] = fmaf(c[4], gb.x, kb.x * vv);
            c[5] = fmaf(c[5], gb.y, kb.y * vv);
            c[6] = fmaf(c[6], gb.z, kb.z * vv);
            c[7] = fmaf(c[7], gb.w, kb.w * vv);

            float p = c[0] * qa.x;
            p = fmaf(c[1], qa.y, p);
            p = fmaf(c[2], qa.z, p);
            p = fmaf(c[3], qa.w, p);
            p = fmaf(c[4], qb.x, p);
            p = fmaf(c[5], qb.y, p);
            p = fmaf(c[6], qb.z, p);
            p = fmaf(c[7], qb.w, p);
            a[i] = p;
        }

        // reduce over the 8-lane v-group (same v, 8 k-slices of this half)
#pragma unroll
        for (int d = 1; d < 8; d <<= 1) {
#pragma unroll
            for (int i = 0; i < SC_GS; ++i)
                a[i] += __shfl_xor_sync(0xffffffffu, a[i], d);
        }

        // combine the two k-halves: warps 4-7 post, warps 0-3 add + write
        if (w >= 4 && (l & 7) == 0) {
#pragma unroll
            for (int i = 0; i < SC_GS; ++i) pb[i][v] = a[i];
        }
        __syncthreads();
        if (w < 4 && (l & 7) == 0) {
            const size_t t8 = (size_t)(g * SC_GS) * VV;
#pragma unroll
            for (int i = 0; i < SC_GS; ++i)
                ob[t8 + (size_t)i * VV] = a[i] + pb[i][v];
        }
    }

    // c_final: (B, K, V). Thread owns k rows k0..k0+8, v col v0+v.
#pragma unroll
    for (int i = 0; i < 8; ++i)
        cfin[((size_t)b * KK + (k0 + i)) * VV + v0 + v] = c[i];
}

// ---------------------------------------------------------------------------
// GEMM2 (small): fp32 SIMT TN GEMM, 128x128 tile, BK=16.
// ---------------------------------------------------------------------------
__global__ __launch_bounds__(256) void gemm_tn(
    const float* __restrict__ A, const float* __restrict__ W,
    const float* __restrict__ bias, float* __restrict__ C,
    int M, int N, int Kd)
{
    __shared__ float As[2][16][136];
    __shared__ float Bs[2][16][136];

    const int tid = threadIdx.x;
    const int m0 = blockIdx.y << 7;
    const int n0 = blockIdx.x << 7;
    const int lr = tid >> 1;
    const int lc = (tid & 1) << 3;

    const float* Aptr = A + (size_t)(m0 + lr) * Kd + lc;
    const float* Wptr = W + (size_t)(n0 + lr) * Kd + lc;

    {
        float4 a0 = *(const float4*)Aptr;
        float4 a1 = *(const float4*)(Aptr + 4);
        float4 b0 = *(const float4*)Wptr;
        float4 b1 = *(const float4*)(Wptr + 4);
#pragma unroll
        for (int cc = 0; cc < 4; ++cc) {
            As[0][lc + cc][lr]     = ((const float*)&a0)[cc];
            As[0][lc + 4 + cc][lr] = ((const float*)&a1)[cc];
            Bs[0][lc + cc][lr]     = ((const float*)&b0)[cc];
            Bs[0][lc + 4 + cc][lr] = ((const float*)&b1)[cc];
        }
    }
    __syncthreads();

    const int ty  = tid >> 4;
    const int tx  = tid & 15;
    const int ar0 = ty << 2;
    const int bc0 = tx << 2;

    float acc[8][8];
#pragma unroll
    for (int i = 0; i < 8; ++i)
#pragma unroll
        for (int j = 0; j < 8; ++j) acc[i][j] = 0.f;

    const int nk = Kd >> 4;
    for (int kt = 0; kt < nk; ++kt) {
        const int buf = kt & 1;
        float4 pa0, pa1, pb0, pb1;
        const bool pf = (kt + 1) < nk;
        if (pf) {
            const float* Ap = Aptr + ((kt + 1) << 4);
            const float* Wp = Wptr + ((kt + 1) << 4);
            pa0 = *(const float4*)Ap;  pa1 = *(const float4*)(Ap + 4);
            pb0 = *(const float4*)Wp;  pb1 = *(const float4*)(Wp + 4);
        }
#pragma unroll
        for (int kk = 0; kk < 16; ++kk) {
            float4 a0 = *(const float4*)&As[buf][kk][ar0];
            float4 a1 = *(const float4*)&As[buf][kk][64 + ar0];
            float4 b0 = *(const float4*)&Bs[buf][kk][bc0];
            float4 b1 = *(const float4*)&Bs[buf][kk][64 + bc0];
            float af[8] = {a0.x,a0.y,a0.z,a0.w,a1.x,a1.y,a1.z,a1.w};
            float bf[8] = {b0.x,b0.y,b0.z,b0.w,b1.x,b1.y,b1.z,b1.w};
#pragma unroll
            for (int i = 0; i < 8; ++i)
#pragma unroll
                for (int j = 0; j < 8; ++j)
                    acc[i][j] = fmaf(af[i], bf[j], acc[i][j]);
        }
        if (pf) {
            const int nb = buf ^ 1;
#pragma unroll
            for (int cc = 0; cc < 4; ++cc) {
                As[nb][lc + cc][lr]     = ((const float*)&pa0)[cc];
                As[nb][lc + 4 + cc][lr] = ((const float*)&pa1)[cc];
                Bs[nb][lc + cc][lr]     = ((const float*)&pb0)[cc];
                Bs[nb][lc + 4 + cc][lr] = ((const float*)&pb1)[cc];
            }
        }
        __syncthreads();
    }

    float bv[8];
#pragma unroll
    for (int j = 0; j < 8; ++j) {
        int n = n0 + ((j < 4) ? (bc0 + j) : (64 + bc0 + (j - 4)));
        bv[j] = bias[n];
    }
#pragma unroll
    for (int i = 0; i < 8; ++i) {
        int m = m0 + ((i < 4) ? (ar0 + i) : (64 + ar0 + (i - 4)));
        float o[8];
#pragma unroll
        for (int j = 0; j < 8; ++j) o[j] = acc[i][j] + bv[j];
        float* cp = C + (size_t)m * N + n0;
        *(float4*)(cp + bc0)      = make_float4(o[0], o[1], o[2], o[3]);
        *(float4*)(cp + 64 + bc0) = make_float4(o[4], o[5], o[6], o[7]);
    }
}

// ---------------------------------------------------------------------------
extern "C" void kernel_launch(void* const* d_in, const int* in_sizes, int n_in,
                              void* d_out, int out_size)
{
    const float* hidden = (const float*)d_in[0];  // (B,T,H)
    const float* W_proj = (const float*)d_in[1];  // (3K+V, H)
    const float* b_proj = (const float*)d_in[2];  // (3K+V,)
    const float* W_out  = (const float*)d_in[3];  // (O, V)
    const float* b_out  = (const float*)d_in[4];  // (O,)
    float* out = (float*)d_out;

    float *qkgv, *obuf, *cdump;
    __nv_bfloat16 *ahi, *alo, *whi, *wlo;
    cudaGetSymbolAddress((void**)&qkgv,  g_qkgv);
    cudaGetSymbolAddress((void**)&obuf,  g_obuf);
    cudaGetSymbolAddress((void**)&cdump, g_cdump);
    cudaGetSymbolAddress((void**)&ahi,   g_ahi);
    cudaGetSymbolAddress((void**)&alo,   g_alo);
    cudaGetSymbolAddress((void**)&whi,   g_whi);
    cudaGetSymbolAddress((void**)&wlo,   g_wlo);

    const size_t out_main = (size_t)BB * TT * OO;
    const size_t out_full = out_main + (size_t)BB * KK * VV;
    float* cfin = ((size_t)out_size >= out_full) ? (out + out_main) : cdump;

    // 0) fp32 -> bf16 hi/lo splits
    {
        int n4 = (MM * HH) / 4;                     // 16,777,216
        cvt_hilo<<<(n4 + 255) / 256, 256>>>(hidden, ahi, alo, n4);
        int w4 = (PP * HH) / 4;                     // 131,072
        cvt_hilo<<<(w4 + 255) / 256, 256>>>(W_proj, whi, wlo, w4);
    }
    // 1) fused projection GEMM (mma.sync, 3-term bf16 split, N-fused tiles)
    {
        cudaFuncSetAttribute(gemm1_mma,
                             cudaFuncAttributeMaxDynamicSharedMemorySize, G1_SMEM);
        dim3 grid(PP / 256, MM / 128);              // (2, 512)
        gemm1_mma<<<grid, 256, G1_SMEM>>>(ahi, alo, whi, wlo, b_proj, qkgv);
    }
    // 2) sequential gated fast-weight scan (k-half x v-quad tiling)
    {
        dim3 grid(BB, VV / 16);                     // (16, 8)
        scan_kernel<<<grid, 256>>>(qkgv, obuf, cfin);
    }
    // 3) output projection
    {
        dim3 grid(OO / 128, MM / 128);              // (1, 512)
        gemm_tn<<<grid, 256>>>(obuf, W_out, b_out, out, MM, OO, VV);
    }
}

// round 15
// speedup vs baseline: 1.3920x; 1.3920x over previous
#include <cuda_runtime.h>
#include <cuda_bf16.h>
#include <math.h>

// Problem dims (fixed by the reference)
#define BB 16
#define TT 4096
#define HH 1024
#define KK 128
#define VV 128
#define OO 128
#define PP 512            // 3K + V
#define MM (BB * TT)      // 65536

// Scratch (static device globals: allocation-free, graph-capturable)
__device__ float g_qkgv[(size_t)BB * TT * PP];   // 128 MB activated projections
__device__ float g_obuf[(size_t)BB * TT * VV];   // 32 MB pre-projection readout
__device__ float g_cdump[(size_t)BB * KK * VV];  // fallback c_final sink
__device__ __nv_bfloat16 g_ahi[(size_t)MM * HH]; // hidden split hi
__device__ __nv_bfloat16 g_alo[(size_t)MM * HH]; // hidden split lo
__device__ __nv_bfloat16 g_whi[(size_t)PP * HH];
__device__ __nv_bfloat16 g_wlo[(size_t)PP * HH];

typedef unsigned long long ull;

// ---------------------------------------------------------------------------
// small PTX helpers
// ---------------------------------------------------------------------------
__device__ __forceinline__ unsigned smem_u32(const void* p) {
    return (unsigned)__cvta_generic_to_shared(p);
}
__device__ __forceinline__ void cp16(void* dst, const void* src) {
    asm volatile("cp.async.cg.shared.global [%0], [%1], 16;\n"
                 :: "r"(smem_u32(dst)), "l"(src));
}
__device__ __forceinline__ void cp_commit() {
    asm volatile("cp.async.commit_group;\n");
}
__device__ __forceinline__ void cp_wait1() {
    asm volatile("cp.async.wait_group 1;\n");
}
__device__ __forceinline__ void ldsm4(unsigned r[4], const void* p) {
    unsigned a = smem_u32(p);
    asm volatile("ldmatrix.sync.aligned.m8n8.x4.shared.b16 {%0,%1,%2,%3}, [%4];\n"
                 : "=r"(r[0]), "=r"(r[1]), "=r"(r[2]), "=r"(r[3]) : "r"(a));
}
__device__ __forceinline__ void mma16816(float d[4], const unsigned a[4],
                                         unsigned b0, unsigned b1) {
    asm volatile("mma.sync.aligned.m16n8k16.row.col.f32.bf16.bf16.f32 "
                 "{%0,%1,%2,%3}, {%4,%5,%6,%7}, {%8,%9}, {%0,%1,%2,%3};\n"
                 : "+f"(d[0]), "+f"(d[1]), "+f"(d[2]), "+f"(d[3])
                 : "r"(a[0]), "r"(a[1]), "r"(a[2]), "r"(a[3]), "r"(b0), "r"(b1));
}
__device__ __forceinline__ unsigned short bfbits(__nv_bfloat16 h) {
    return ((__nv_bfloat16_raw)h).x;
}

// ---------------------------------------------------------------------------
// fp32 -> (hi, lo) bf16 split. x = hi + lo + O(2^-16 |x|).
// ---------------------------------------------------------------------------
__global__ __launch_bounds__(256) void cvt_hilo(
    const float* __restrict__ x, __nv_bfloat16* __restrict__ hi,
    __nv_bfloat16* __restrict__ lo, int n4)
{
    int i = blockIdx.x * blockDim.x + threadIdx.x;
    if (i >= n4) return;
    float4 xv = ((const float4*)x)[i];
    float xs[4] = {xv.x, xv.y, xv.z, xv.w};
    unsigned short hb[4], lb[4];
#pragma unroll
    for (int j = 0; j < 4; ++j) {
        __nv_bfloat16 h = __float2bfloat16(xs[j]);
        float r = xs[j] - __bfloat162float(h);   // exact residual
        __nv_bfloat16 l = __float2bfloat16(r);
        hb[j] = bfbits(h);
        lb[j] = bfbits(l);
    }
    uint2 uh = make_uint2(hb[0] | ((unsigned)hb[1] << 16),
                          hb[2] | ((unsigned)hb[3] << 16));
    uint2 ul = make_uint2(lb[0] | ((unsigned)lb[1] << 16),
                          lb[2] | ((unsigned)lb[3] << 16));
    ((uint2*)hi)[i] = uh;
    ((uint2*)lo)[i] = ul;
}

// ---------------------------------------------------------------------------
// GEMM1 v2 (round-13, unchanged): qkgv[M,512] = act( A @ W^T + bias )
// bf16 hi/lo split, 3-term mma.sync, CTA tile 128m x 256n, BK=32,
// 8 warps (4m x 2n), warp tile 32x128, cp.async 3-stage ring.
// ---------------------------------------------------------------------------
#define G1_STRIDE 40                       // bf16 per smem row (32 + 8 pad)
#define G1_PLANE_A (128 * G1_STRIDE)       // 5120 bf16
#define G1_PLANE_W (256 * G1_STRIDE)       // 10240 bf16
#define G1_STAGE  (2 * G1_PLANE_A + 2 * G1_PLANE_W)   // 30720 bf16
#define G1_SMEM   (3 * G1_STAGE * 2)       // 184320 B

__global__ __launch_bounds__(256) void gemm1_mma(
    const __nv_bfloat16* __restrict__ Ah, const __nv_bfloat16* __restrict__ Al,
    const __nv_bfloat16* __restrict__ Wh, const __nv_bfloat16* __restrict__ Wl,
    const float* __restrict__ bias, float* __restrict__ C)
{
    extern __shared__ __nv_bfloat16 sm[];
    const int tid  = threadIdx.x;
    const int m0   = blockIdx.y << 7;
    const int n0   = blockIdx.x << 8;      // 256-wide n tile
    const int lane = tid & 31;
    const int warp = tid >> 5;
    const int wm   = (warp & 3) << 5;      // warp m offset (0..96)
    const int wn   = (warp >> 2) << 7;     // warp n offset (0 or 128)

    const __nv_bfloat16* srcs[4] = {
        Ah + (size_t)m0 * HH, Al + (size_t)m0 * HH,
        Wh + (size_t)n0 * HH, Wl + (size_t)n0 * HH };
    const int poff[4]  = {0, G1_PLANE_A, 2 * G1_PLANE_A, 2 * G1_PLANE_A + G1_PLANE_W};

    // load one k32 block (3072 16B chunks) into stage st
    auto issue = [&](int kt, int st) {
        __nv_bfloat16* sb = sm + st * G1_STAGE;
#pragma unroll
        for (int h = 0; h < 12; ++h) {
            int c    = tid + (h << 8);           // 0..3071
            int grow = c >> 2;                   // 0..767
            int col  = (c & 3) << 3;
            int p    = (grow < 256) ? (grow >> 7) : (2 + ((grow - 256) >> 8));
            int r    = (grow < 256) ? (grow & 127) : ((grow - 256) & 255);
            cp16(sb + poff[p] + r * G1_STRIDE + col,
                 srcs[p] + (size_t)r * HH + kt * 32 + col);
        }
        cp_commit();
    };

    float acc[2][16][4];
#pragma unroll
    for (int im = 0; im < 2; ++im)
#pragma unroll
        for (int j = 0; j < 16; ++j)
#pragma unroll
            for (int r = 0; r < 4; ++r) acc[im][j][r] = 0.f;

    issue(0, 0);
    issue(1, 1);

    const int arow  = lane & 15;
    const int acolb = (lane >> 4) << 3;
    const int brow  = ((lane & 16) >> 1) + (lane & 7);
    const int bcolb = ((lane >> 3) & 1) << 3;

    const int nk = HH / 32;                // 32
    for (int kt = 0; kt < nk; ++kt) {
        cp_wait1();
        __syncthreads();
        const __nv_bfloat16* st  = sm + (kt % 3) * G1_STAGE;
        const __nv_bfloat16* sAh = st;
        const __nv_bfloat16* sAl = st + G1_PLANE_A;
        const __nv_bfloat16* sWh = st + 2 * G1_PLANE_A;
        const __nv_bfloat16* sWl = st + 2 * G1_PLANE_A + G1_PLANE_W;
#pragma unroll
        for (int ks = 0; ks < 2; ++ks) {
            const int ko = ks << 4;
            unsigned aH[2][4], aL[2][4];
#pragma unroll
            for (int im = 0; im < 2; ++im) {
                int r = wm + (im << 4) + arow;
                ldsm4(aH[im], sAh + r * G1_STRIDE + ko + acolb);
                ldsm4(aL[im], sAl + r * G1_STRIDE + ko + acolb);
            }
#pragma unroll
            for (int ng = 0; ng < 8; ++ng) {
                int r = wn + (ng << 4) + brow;
                unsigned bh[4], bl[4];
                ldsm4(bh, sWh + r * G1_STRIDE + ko + bcolb);
                ldsm4(bl, sWl + r * G1_STRIDE + ko + bcolb);
#pragma unroll
                for (int im = 0; im < 2; ++im) {
                    mma16816(acc[im][ng * 2],     aH[im], bh[0], bh[1]);
                    mma16816(acc[im][ng * 2 + 1], aH[im], bh[2], bh[3]);
                    mma16816(acc[im][ng * 2],     aH[im], bl[0], bl[1]);
                    mma16816(acc[im][ng * 2 + 1], aH[im], bl[2], bl[3]);
                    mma16816(acc[im][ng * 2],     aL[im], bh[0], bh[1]);
                    mma16816(acc[im][ng * 2 + 1], aL[im], bh[2], bh[3]);
                }
            }
        }
        if (kt + 2 < nk) issue(kt + 2, (kt + 2) % 3);
        else             cp_commit();
    }

    // epilogue: bias + activation (block 0:q id, 1:k sig, 2:g sig, 3:v tanh)
    const int nblk = (n0 + wn) >> 7;
    const int act  = (nblk == 0) ? 0 : ((nblk == 3) ? 2 : 1);
    const int r0     = m0 + wm + (lane >> 2);
    const int c0base = n0 + wn + ((lane & 3) << 1);
#pragma unroll
    for (int j = 0; j < 16; ++j) {
        int col = c0base + (j << 3);
        float b0 = bias[col], b1 = bias[col + 1];
#pragma unroll
        for (int im = 0; im < 2; ++im) {
            int rb = r0 + (im << 4);
            float v0 = acc[im][j][0] + b0, v1 = acc[im][j][1] + b1;
            float v2 = acc[im][j][2] + b0, v3 = acc[im][j][3] + b1;
            if (act == 1) {
                v0 = 1.f / (1.f + __expf(-v0)); v1 = 1.f / (1.f + __expf(-v1));
                v2 = 1.f / (1.f + __expf(-v2)); v3 = 1.f / (1.f + __expf(-v3));
            } else if (act == 2) {
                v0 = tanhf(v0); v1 = tanhf(v1); v2 = tanhf(v2); v3 = tanhf(v3);
            }
            *(float2*)(C + (size_t)rb * PP + col)       = make_float2(v0, v1);
            *(float2*)(C + (size_t)(rb + 8) * PP + col) = make_float2(v2, v3);
        }
    }
}

// ---------------------------------------------------------------------------
// Sequential scan v5: 128 threads / 4 warps (halved crossbar duplication).
// Warp w owns v-quad {v0+4w..+3}; lane l owns k's {4l..4l+3} (contiguous
// float4 -> conflict-free phases). State c[4][4] in registers.
// Crossbar/step: 3 ops x 4 phases x 4 warps = 48 phases (round 13: 104).
// Readout: per-warp partials for 4 v's, full 32-lane butterfly (all 128 k
// inside one warp -> no cross-warp combine). 8-step groups, 3-ring cp.async,
// refill right after the top barrier.
// Lesson from R14 baked in: smem broadcast dedups ONLY within an 8-lane
// phase; never duplicate data across octets of a warp.
// ---------------------------------------------------------------------------
#define SC_GROUPS 3
#define SC_GS     8                        // steps per group
#define SC_STAGES (SC_GROUPS * SC_GS)      // 24

__global__ __launch_bounds__(128) void scan_kernel(
    const float* __restrict__ qkgv, float* __restrict__ obuf,
    float* __restrict__ cfin)
{
    const int b   = blockIdx.x;
    const int v0  = blockIdx.y << 4;
    const int tid = threadIdx.x;
    const int w   = tid >> 5;            // warp: v-quad 4w..4w+3
    const int l   = tid & 31;            // lane: k's 4l..4l+3
    const int k0  = l << 2;
    const int vb  = w << 2;              // v-quad base within tile

    __shared__ float s[SC_STAGES][400];  // [q:128 | k:128 | g:128 | v-tile:16]

    const float* base = qkgv + (size_t)b * TT * PP;
    float* ob = obuf + (size_t)b * TT * VV + v0 + vb;

    float c[4][4];                       // c[k_sub][v_sub]
#pragma unroll
    for (int i = 0; i < 4; ++i)
#pragma unroll
        for (int j = 0; j < 4; ++j) c[i][j] = 0.f;

    // 100 copy threads x 16B per step
    const bool cpr = (tid < 100);
    const int goff = (tid < 96) ? (tid << 2) : (384 + v0 + ((tid - 96) << 2));
    const int soff = (tid < 96) ? (tid << 2) : (384 + ((tid - 96) << 2));

    auto issue_group = [&](int g) {
        if (cpr) {
            const int sb = (g % SC_GROUPS) * SC_GS;
            const float* p = base + (size_t)(g * SC_GS) * PP + goff;
#pragma unroll
            for (int i = 0; i < SC_GS; ++i)
                cp16(&s[sb + i][soff], p + (size_t)i * PP);
        }
        cp_commit();
    };

    issue_group(0);
    issue_group(1);

    const int NG = TT / SC_GS;           // 512 groups
    for (int g = 0; g < NG; ++g) {
        cp_wait1();                      // group g complete
        __syncthreads();

        // refill: group g+2 -> slots of group g-1 (readers passed barrier)
        if (g + 2 < NG) issue_group(g + 2);
        else            cp_commit();

        const int sb = (g % SC_GROUPS) * SC_GS;

        float a[SC_GS][4];
#pragma unroll
        for (int i = 0; i < SC_GS; ++i) {
            const float* st = s[sb + i];
            float4 q  = *(const float4*)&st[k0];
            float4 kk = *(const float4*)&st[128 + k0];
            float4 gg = *(const float4*)&st[256 + k0];
            float4 vv = *(const float4*)&st[384 + vb];   // warp-broadcast
            const float qx[4] = {q.x, q.y, q.z, q.w};
            const float kx[4] = {kk.x, kk.y, kk.z, kk.w};
            const float gx[4] = {gg.x, gg.y, gg.z, gg.w};
            const float vx[4] = {vv.x, vv.y, vv.z, vv.w};

#pragma unroll
            for (int ii = 0; ii < 4; ++ii)
#pragma unroll
                for (int j = 0; j < 4; ++j)
                    c[ii][j] = fmaf(c[ii][j], gx[ii], kx[ii] * vx[j]);

#pragma unroll
            for (int j = 0; j < 4; ++j) {
                float p = c[0][j] * qx[0];
                p = fmaf(c[1][j], qx[1], p);
                p = fmaf(c[2][j], qx[2], p);
                p = fmaf(c[3][j], qx[3], p);
                a[i][j] = p;
            }
        }

        // 32 interleaved butterflies (8 steps x 4 v), reduce over all 128 k
#pragma unroll
        for (int d = 1; d < 32; d <<= 1) {
#pragma unroll
            for (int i = 0; i < SC_GS; ++i)
#pragma unroll
                for (int j = 0; j < 4; ++j)
                    a[i][j] += __shfl_xor_sync(0xffffffffu, a[i][j], d);
        }
        if (l == 0) {
            const size_t t8 = (size_t)(g * SC_GS) * VV;
#pragma unroll
            for (int i = 0; i < SC_GS; ++i)
                *(float4*)&ob[t8 + (size_t)i * VV] =
                    make_float4(a[i][0], a[i][1], a[i][2], a[i][3]);
        }
    }

    // c_final: (B, K, V). Thread owns k rows 4l..4l+3, v cols v0+4w..+3.
#pragma unroll
    for (int i = 0; i < 4; ++i)
        *(float4*)&cfin[((size_t)b * KK + (k0 + i)) * VV + v0 + vb] =
            make_float4(c[i][0], c[i][1], c[i][2], c[i][3]);
}

// ---------------------------------------------------------------------------
// GEMM2 (small): fp32 SIMT TN GEMM, 128x128 tile, BK=16.
// ---------------------------------------------------------------------------
__global__ __launch_bounds__(256) void gemm_tn(
    const float* __restrict__ A, const float* __restrict__ W,
    const float* __restrict__ bias, float* __restrict__ C,
    int M, int N, int Kd)
{
    __shared__ float As[2][16][136];
    __shared__ float Bs[2][16][136];

    const int tid = threadIdx.x;
    const int m0 = blockIdx.y << 7;
    const int n0 = blockIdx.x << 7;
    const int lr = tid >> 1;
    const int lc = (tid & 1) << 3;

    const float* Aptr = A + (size_t)(m0 + lr) * Kd + lc;
    const float* Wptr = W + (size_t)(n0 + lr) * Kd + lc;

    {
        float4 a0 = *(const float4*)Aptr;
        float4 a1 = *(const float4*)(Aptr + 4);
        float4 b0 = *(const float4*)Wptr;
        float4 b1 = *(const float4*)(Wptr + 4);
#pragma unroll
        for (int cc = 0; cc < 4; ++cc) {
            As[0][lc + cc][lr]     = ((const float*)&a0)[cc];
            As[0][lc + 4 + cc][lr] = ((const float*)&a1)[cc];
            Bs[0][lc + cc][lr]     = ((const float*)&b0)[cc];
            Bs[0][lc + 4 + cc][lr] = ((const float*)&b1)[cc];
        }
    }
    __syncthreads();

    const int ty  = tid >> 4;
    const int tx  = tid & 15;
    const int ar0 = ty << 2;
    const int bc0 = tx << 2;

    float acc[8][8];
#pragma unroll
    for (int i = 0; i < 8; ++i)
#pragma unroll
        for (int j = 0; j < 8; ++j) acc[i][j] = 0.f;

    const int nk = Kd >> 4;
    for (int kt = 0; kt < nk; ++kt) {
        const int buf = kt & 1;
        float4 pa0, pa1, pb0, pb1;
        const bool pf = (kt + 1) < nk;
        if (pf) {
            const float* Ap = Aptr + ((kt + 1) << 4);
            const float* Wp = Wptr + ((kt + 1) << 4);
            pa0 = *(const float4*)Ap;  pa1 = *(const float4*)(Ap + 4);
            pb0 = *(const float4*)Wp;  pb1 = *(const float4*)(Wp + 4);
        }
#pragma unroll
        for (int kk = 0; kk < 16; ++kk) {
            float4 a0 = *(const float4*)&As[buf][kk][ar0];
            float4 a1 = *(const float4*)&As[buf][kk][64 + ar0];
            float4 b0 = *(const float4*)&Bs[buf][kk][bc0];
            float4 b1 = *(const float4*)&Bs[buf][kk][64 + bc0];
            float af[8] = {a0.x,a0.y,a0.z,a0.w,a1.x,a1.y,a1.z,a1.w};
            float bf[8] = {b0.x,b0.y,b0.z,b0.w,b1.x,b1.y,b1.z,b1.w};
#pragma unroll
            for (int i = 0; i < 8; ++i)
#pragma unroll
                for (int j = 0; j < 8; ++j)
                    acc[i][j] = fmaf(af[i], bf[j], acc[i][j]);
        }
        if (pf) {
            const int nb = buf ^ 1;
#pragma unroll
            for (int cc = 0; cc < 4; ++cc) {
                As[nb][lc + cc][lr]     = ((const float*)&pa0)[cc];
                As[nb][lc + 4 + cc][lr] = ((const float*)&pa1)[cc];
                Bs[nb][lc + cc][lr]     = ((const float*)&pb0)[cc];
                Bs[nb][lc + 4 + cc][lr] = ((const float*)&pb1)[cc];
            }
        }
        __syncthreads();
    }

    float bv[8];
#pragma unroll
    for (int j = 0; j < 8; ++j) {
        int n = n0 + ((j < 4) ? (bc0 + j) : (64 + bc0 + (j - 4)));
        bv[j] = bias[n];
    }
#pragma unroll
    for (int i = 0; i < 8; ++i) {
        int m = m0 + ((i < 4) ? (ar0 + i) : (64 + ar0 + (i - 4)));
        float o[8];
#pragma unroll
        for (int j = 0; j < 8; ++j) o[j] = acc[i][j] + bv[j];
        float* cp = C + (size_t)m * N + n0;
        *(float4*)(cp + bc0)      = make_float4(o[0], o[1], o[2], o[3]);
        *(float4*)(cp + 64 + bc0) = make_float4(o[4], o[5], o[6], o[7]);
    }
}

// ---------------------------------------------------------------------------
extern "C" void kernel_launch(void* const* d_in, const int* in_sizes, int n_in,
                              void* d_out, int out_size)
{
    const float* hidden = (const float*)d_in[0];  // (B,T,H)
    const float* W_proj = (const float*)d_in[1];  // (3K+V, H)
    const float* b_proj = (const float*)d_in[2];  // (3K+V,)
    const float* W_out  = (const float*)d_in[3];  // (O, V)
    const float* b_out  = (const float*)d_in[4];  // (O,)
    float* out = (float*)d_out;

    float *qkgv, *obuf, *cdump;
    __nv_bfloat16 *ahi, *alo, *whi, *wlo;
    cudaGetSymbolAddress((void**)&qkgv,  g_qkgv);
    cudaGetSymbolAddress((void**)&obuf,  g_obuf);
    cudaGetSymbolAddress((void**)&cdump, g_cdump);
    cudaGetSymbolAddress((void**)&ahi,   g_ahi);
    cudaGetSymbolAddress((void**)&alo,   g_alo);
    cudaGetSymbolAddress((void**)&whi,   g_whi);
    cudaGetSymbolAddress((void**)&wlo,   g_wlo);

    const size_t out_main = (size_t)BB * TT * OO;
    const size_t out_full = out_main + (size_t)BB * KK * VV;
    float* cfin = ((size_t)out_size >= out_full) ? (out + out_main) : cdump;

    // 0) fp32 -> bf16 hi/lo splits
    {
        int n4 = (MM * HH) / 4;                     // 16,777,216
        cvt_hilo<<<(n4 + 255) / 256, 256>>>(hidden, ahi, alo, n4);
        int w4 = (PP * HH) / 4;                     // 131,072
        cvt_hilo<<<(w4 + 255) / 256, 256>>>(W_proj, whi, wlo, w4);
    }
    // 1) fused projection GEMM (mma.sync, 3-term bf16 split, N-fused tiles)
    {
        cudaFuncSetAttribute(gemm1_mma,
                             cudaFuncAttributeMaxDynamicSharedMemorySize, G1_SMEM);
        dim3 grid(PP / 256, MM / 128);              // (2, 512)
        gemm1_mma<<<grid, 256, G1_SMEM>>>(ahi, alo, whi, wlo, b_proj, qkgv);
    }
    // 2) sequential gated fast-weight scan (4 warps, 4k x 4v per thread)
    {
        dim3 grid(BB, VV / 16);                     // (16, 8)
        scan_kernel<<<grid, 128>>>(qkgv, obuf, cfin);
    }
    // 3) output projection
    {
        dim3 grid(OO / 128, MM / 128);              // (1, 512)
        gemm_tn<<<grid, 256>>>(obuf, W_out, b_out, out, MM, OO, VV);
    }
}